// round 2
// baseline (speedup 1.0000x reference)
#include <cuda_runtime.h>

#define TPB 256

// ---------------- Problem constants ----------------
// B=4, U=64, V=256, DIM=768, CODE=384, INNER=512, HEADS=8, HD=64

struct Params {
    const float *recv, *codes, *send;
    const float *lnrg, *lnrb, *lnsg, *lnsb;
    const float *Wq, *bq, *Wmq, *Wk, *bk, *Wmk;
    const float *Wv, *bv, *Wmv, *We, *be, *Wme, *gamma;
    float* out;
    int nb;
};

// ---------------- Scratch (device globals; no allocs) ----------------
__device__ float g_r  [256 * 768];
__device__ float g_s  [1024 * 768];
__device__ float g_mq [256 * 768];
__device__ float g_mk [256 * 768];
__device__ float g_mv [256 * 768];
__device__ float g_me [256 * 512];
__device__ float g_q  [256 * 512];
__device__ float g_qbk[256 * 8];
__device__ float g_Ak [4 * 512 * 768];
__device__ float g_w  [4 * 512 * 256];
__device__ float g_Tm [8 * 256 * 768];
__device__ float g_msg[256 * 512];

__device__ unsigned g_barcnt = 0;
__device__ unsigned g_bargen = 0;

// Software grid barrier. Safe because grid size == resident-block count
// (grid = occupancyMaxActiveBlocksPerMultiprocessor * numSMs).
__device__ __forceinline__ void grid_bar(int nb) {
    __syncthreads();
    if (threadIdx.x == 0) {
        __threadfence();
        unsigned gen = *(volatile unsigned*)&g_bargen;
        unsigned t = atomicAdd(&g_barcnt, 1u);
        if (t == (unsigned)(nb - 1)) {
            atomicExch(&g_barcnt, 0u);
            __threadfence();
            atomicExch(&g_bargen, gen + 1u);
        } else {
            while (*(volatile unsigned*)&g_bargen == gen) { __nanosleep(32); }
        }
        __threadfence();
    }
    __syncthreads();
}

// ---------------- warp LayerNorm over a 768-row ----------------
__device__ __forceinline__ void ln_row(const float* __restrict__ x,
                                       const float* __restrict__ g,
                                       const float* __restrict__ b,
                                       float* __restrict__ o) {
    int lane = threadIdx.x & 31;
    float v[24];
    float s = 0.f, q = 0.f;
    #pragma unroll
    for (int i = 0; i < 24; i++) {
        v[i] = x[lane + 32 * i];
        s += v[i];
        q += v[i] * v[i];
    }
    #pragma unroll
    for (int off = 16; off; off >>= 1) {
        s += __shfl_xor_sync(0xffffffffu, s, off);
        q += __shfl_xor_sync(0xffffffffu, q, off);
    }
    float mu  = s * (1.f / 768.f);
    float inv = rsqrtf(q * (1.f / 768.f) - mu * mu + 1e-5f);
    #pragma unroll
    for (int i = 0; i < 24; i++) {
        int idx = lane + 32 * i;
        o[idx] = (v[i] - mu) * inv * g[idx] + b[idx];
    }
}

// ---------------- 32x32 tile GEMM done by a 64-thread group ----------------
// Each thread: 4x4 outputs (tx,ty in 8x8 grid). K multiple of 16.
// BKFAST=true  -> B element layout row-major in K  (NT-style: lb(n,k))
// BKFAST=false -> B element layout row-major in N  (NN-style: lb(n,k))
template<bool BKFAST, class AL, class BL, class EP>
__device__ __forceinline__ void tile32(int K, float (*As)[36], float (*Bs)[36],
                                       int barid, AL la, BL lb, EP ep) {
    int lane = threadIdx.x & 63;
    int tx = lane & 7, ty = lane >> 3;
    float acc[4][4] = {};
    for (int k0 = 0; k0 < K; k0 += 16) {
        #pragma unroll
        for (int i = 0; i < 8; i++) {            // A: k-fast fill (coalesced for row-major-K A)
            int e = lane + 64 * i;
            As[e & 15][e >> 4] = la(e >> 4, k0 + (e & 15));
        }
        if (BKFAST) {
            #pragma unroll
            for (int i = 0; i < 8; i++) {        // B row-major in K: k-fast fill
                int e = lane + 64 * i;
                Bs[e & 15][e >> 4] = lb(e >> 4, k0 + (e & 15));
            }
        } else {
            #pragma unroll
            for (int i = 0; i < 8; i++) {        // B row-major in N: n-fast fill (coalesced)
                int e = lane + 64 * i;
                Bs[e >> 5][e & 31] = lb(e & 31, k0 + (e >> 5));
            }
        }
        asm volatile("bar.sync %0, 64;" :: "r"(barid) : "memory");
        #pragma unroll
        for (int kk = 0; kk < 16; kk++) {
            float4 a4 = *(const float4*)(&As[kk][ty * 4]);
            float4 b4 = *(const float4*)(&Bs[kk][tx * 4]);
            float av[4] = {a4.x, a4.y, a4.z, a4.w};
            float bv[4] = {b4.x, b4.y, b4.z, b4.w};
            #pragma unroll
            for (int i = 0; i < 4; i++)
                #pragma unroll
                for (int j = 0; j < 4; j++)
                    acc[i][j] += av[i] * bv[j];
        }
        asm volatile("bar.sync %0, 64;" :: "r"(barid) : "memory");
    }
    #pragma unroll
    for (int i = 0; i < 4; i++)
        #pragma unroll
        for (int j = 0; j < 4; j++)
            ep(ty * 4 + i, tx * 4 + j, acc[i][j]);
}

// ---------------- The single persistent kernel ----------------
__global__ void __launch_bounds__(TPB, 2) fused_kernel(Params P) {
    __shared__ float smA[4][16][36];
    __shared__ float smB[4][16][36];
    const int nb = P.nb;
    const int bid = blockIdx.x;
    const int grp = threadIdx.x >> 6;
    const int barid = grp + 1;
    float (*As)[36] = smA[grp];
    float (*Bs)[36] = smB[grp];
    const int gid = bid * 4 + grp;
    const int ng  = nb * 4;
    const int wglob = bid * 8 + (threadIdx.x >> 5);
    const int nwarp = nb * 8;
    const int lane32 = threadIdx.x & 31;

    // ---- Stage 1: both LayerNorms (warp/row) + 4 modulation GEMMs ----
    for (int r = wglob; r < 1280; r += nwarp) {
        if (r < 256) ln_row(P.recv + r * 768, P.lnrg, P.lnrb, g_r + r * 768);
        else {
            int rr = r - 256;
            ln_row(P.send + rr * 768, P.lnsg, P.lnsb, g_s + rr * 768);
        }
    }
    for (int t = gid; t < 704; t += ng) {
        const float* W; float* O; int N; int lt;
        if (t < 192)      { W = P.Wmq; O = g_mq; N = 768; lt = t; }
        else if (t < 384) { W = P.Wmk; O = g_mk; N = 768; lt = t - 192; }
        else if (t < 576) { W = P.Wmv; O = g_mv; N = 768; lt = t - 384; }
        else              { W = P.Wme; O = g_me; N = 512; lt = t - 576; }
        int m0 = (lt & 7) * 32, n0 = (lt >> 3) * 32;
        tile32<false>(384, As, Bs, barid,
            [&](int m, int k) { return P.codes[(m0 + m) * 384 + k]; },
            [&](int n, int k) { return W[k * N + n0 + n]; },
            [&](int m, int n, float a) { O[(m0 + m) * N + n0 + n] = a; });
    }
    grid_bar(nb);

    // ---- Stage 2: q = (r*(1+mq)) @ Wq + bq   [256,768]x[768,512] ----
    for (int t = gid; t < 128; t += ng) {
        int m0 = (t & 7) * 32, n0 = (t >> 3) * 32;
        tile32<false>(768, As, Bs, barid,
            [&](int m, int k) { int i = (m0 + m) * 768 + k; return g_r[i] * (1.f + g_mq[i]); },
            [&](int n, int k) { return P.Wq[k * 512 + n0 + n]; },
            [&](int m, int n, float a) { g_q[(m0 + m) * 512 + n0 + n] = a + P.bq[n0 + n]; });
    }
    grid_bar(nb);

    // ---- Stage 3: qbk dots + Ak = (Wk_h q_h)*(1+mk)  (per-head NT, K=64) ----
    for (int w = wglob; w < 2048; w += nwarp) {
        int bu = w >> 3, h = w & 7;
        const float* qp = g_q + bu * 512 + h * 64;
        const float* bp = P.bk + h * 64;
        float s = qp[lane32] * bp[lane32] + qp[lane32 + 32] * bp[lane32 + 32];
        #pragma unroll
        for (int off = 16; off; off >>= 1) s += __shfl_xor_sync(0xffffffffu, s, off);
        if (lane32 == 0) g_qbk[bu * 8 + h] = s;
    }
    for (int t = gid; t < 1536; t += ng) {
        int h = t / 192, lt = t % 192;
        int m0 = (lt & 7) * 32, n0 = (lt >> 3) * 32;
        tile32<true>(64, As, Bs, barid,
            [&](int m, int k) { return g_q[(m0 + m) * 512 + h * 64 + k]; },
            [&](int n, int k) { return P.Wk[(n0 + n) * 512 + h * 64 + k]; },
            [&](int m, int n, float a) {
                int mg = m0 + m; int b = mg >> 6, u = mg & 63;
                g_Ak[b * 393216 + (h * 64 + u) * 768 + n0 + n] =
                    a * (1.f + g_mk[mg * 768 + n0 + n]);
            });
    }
    grid_bar(nb);

    // ---- Stage 4: scores = (Ak @ s^T + qbk)/8  (per-batch NT, K=768) ----
    for (int t = gid; t < 512; t += ng) {
        int b = t >> 7, lt = t & 127;
        int m0 = (lt & 15) * 32, n0 = (lt >> 4) * 32;
        tile32<true>(768, As, Bs, barid,
            [&](int m, int k) { return g_Ak[b * 393216 + (m0 + m) * 768 + k]; },
            [&](int n, int k) { return g_s[(b * 256 + n0 + n) * 768 + k]; },
            [&](int m, int n, float a) {
                int mg = m0 + m; int h = mg >> 6, u = mg & 63;
                g_w[b * 131072 + mg * 256 + n0 + n] =
                    (a + g_qbk[(b * 64 + u) * 8 + h]) * 0.125f;
            });
    }
    grid_bar(nb);

    // ---- Stage 5: softmax over v (warp/row, 2048 rows of 256) ----
    for (int r = wglob; r < 2048; r += nwarp) {
        float* p = g_w + r * 256;
        float v[8], mx = -1e30f;
        #pragma unroll
        for (int i = 0; i < 8; i++) { v[i] = p[lane32 + 32 * i]; mx = fmaxf(mx, v[i]); }
        #pragma unroll
        for (int off = 16; off; off >>= 1) mx = fmaxf(mx, __shfl_xor_sync(0xffffffffu, mx, off));
        float sm = 0.f;
        #pragma unroll
        for (int i = 0; i < 8; i++) { v[i] = expf(v[i] - mx); sm += v[i]; }
        #pragma unroll
        for (int off = 16; off; off >>= 1) sm += __shfl_xor_sync(0xffffffffu, sm, off);
        float inv = 1.f / sm;
        #pragma unroll
        for (int i = 0; i < 8; i++) p[lane32 + 32 * i] = v[i] * inv;
    }
    grid_bar(nb);

    // ---- Stage 6: Tm = (w @ s)*(1+mv), remapped per-head (per-batch NN, K=256) ----
    for (int t = gid; t < 1536; t += ng) {
        int b = t / 384, lt = t % 384;
        int m0 = (lt & 15) * 32, n0 = (lt >> 4) * 32;
        tile32<false>(256, As, Bs, barid,
            [&](int m, int k) { return g_w[b * 131072 + (m0 + m) * 256 + k]; },
            [&](int n, int k) { return g_s[(b * 256 + k) * 768 + n0 + n]; },
            [&](int m, int n, float a) {
                int mg = m0 + m; int h = mg >> 6, u = mg & 63; int bu = b * 64 + u;
                g_Tm[(h * 256 + bu) * 768 + n0 + n] = a * (1.f + g_mv[bu * 768 + n0 + n]);
            });
    }
    grid_bar(nb);

    // ---- Stage 7: msg = (Tm_h @ Wv_h + bv)*(1+me)  (per-head NN, K=768) ----
    for (int t = gid; t < 128; t += ng) {
        int h = t >> 4, lt = t & 15;
        int m0 = (lt & 7) * 32, n0 = (lt >> 3) * 32;
        tile32<false>(768, As, Bs, barid,
            [&](int m, int k) { return g_Tm[(h * 256 + m0 + m) * 768 + k]; },
            [&](int n, int k) { return P.Wv[k * 512 + h * 64 + n0 + n]; },
            [&](int m, int n, float a) {
                int c = h * 64 + n0 + n; int mg = m0 + m;
                g_msg[mg * 512 + c] = (a + P.bv[c]) * (1.f + g_me[mg * 512 + c]);
            });
    }
    grid_bar(nb);

    // ---- Stage 8: out = recv + (msg @ We + be)*gamma  [256,512]x[512,768] ----
    for (int t = gid; t < 192; t += ng) {
        int m0 = (t & 7) * 32, n0 = (t >> 3) * 32;
        tile32<false>(512, As, Bs, barid,
            [&](int m, int k) { return g_msg[(m0 + m) * 512 + k]; },
            [&](int n, int k) { return P.We[k * 768 + n0 + n]; },
            [&](int m, int n, float a) {
                int mg = m0 + m, c = n0 + n;
                P.out[mg * 768 + c] = P.recv[mg * 768 + c] + (a + P.be[c]) * P.gamma[c];
            });
    }
}

// ---------------- Host launcher ----------------
extern "C" void kernel_launch(void* const* d_in, const int* in_sizes, int n_in,
                              void* d_out, int out_size) {
    (void)in_sizes; (void)n_in; (void)out_size;
    Params P;
    P.recv  = (const float*)d_in[0];
    P.codes = (const float*)d_in[1];
    P.send  = (const float*)d_in[2];
    P.lnrg  = (const float*)d_in[3];
    P.lnrb  = (const float*)d_in[4];
    P.lnsg  = (const float*)d_in[5];
    P.lnsb  = (const float*)d_in[6];
    P.Wq  = (const float*)d_in[7];
    P.bq  = (const float*)d_in[8];
    P.Wmq = (const float*)d_in[9];
    P.Wk  = (const float*)d_in[10];
    P.bk  = (const float*)d_in[11];
    P.Wmk = (const float*)d_in[12];
    P.Wv  = (const float*)d_in[13];
    P.bv  = (const float*)d_in[14];
    P.Wmv = (const float*)d_in[15];
    P.We  = (const float*)d_in[16];
    P.be  = (const float*)d_in[17];
    P.Wme = (const float*)d_in[18];
    P.gamma = (const float*)d_in[19];
    P.out = (float*)d_out;

    int occ = 0;
    cudaOccupancyMaxActiveBlocksPerMultiprocessor(&occ, fused_kernel, TPB, 0);
    if (occ < 1) occ = 1;
    int dev = 0;
    cudaGetDevice(&dev);
    int sms = 0;
    cudaDeviceGetAttribute(&sms, cudaDevAttrMultiProcessorCount, dev);
    if (sms < 1) sms = 1;
    int nb = occ * sms;
    if (nb > 1536) nb = 1536;   // cap; work loops handle any nb
    P.nb = nb;

    fused_kernel<<<nb, TPB>>>(P);
}